// round 2
// baseline (speedup 1.0000x reference)
#include <cuda_runtime.h>

// Integrate-and-fire, equivalent sequential form of the reference:
//   per neuron (b,h1,h2,c):  v=0 at t=0 and t=100 (chunk boundary);
//   for t: v += x[t]; if (v > 2.0f) { spike=1; v=0; } else spike=0;
// Output layout: out[b][t][h2][c][h1]  (swapaxes(spikes, 1, -1))
//
// Layout constants for input (4, 200, 64, 64, 8):
//   in[b][t][h1][h2][c] : stride_t = 64*64*8 = 32768, stride_h1 = 512,
//                         stride_h2 = 8, stride_c = 1
// Output (4, 200, 64, 8, 64):
//   out[b][t][h2][c][h1]: stride_t = 32768, stride_h2 = 512,
//                         stride_c = 64, stride_h1 = 1

#define T_STRIDE 32768
#define CHUNK    100
#define KT       10      // timesteps staged per shared-memory tile

__global__ __launch_bounds__(512)
void iaf_kernel(const float* __restrict__ in, float* __restrict__ out) {
    // grid: 512 blocks = b(4) x h2(64) x chunk(2)
    const int bid   = blockIdx.x;
    const int b     = bid >> 7;
    const int h2    = (bid >> 1) & 63;
    const int chunk = bid & 1;
    const int t_base = chunk * CHUNK;

    const int tid = threadIdx.x;

    // Load mapping: consecutive tids cover c fastest -> each warp reads
    // 4 fully-used 32B sectors (8 floats each) per load.
    const int h1_l = tid >> 3;
    const int c_l  = tid & 7;

    // Scan/store mapping: consecutive tids cover h1 fastest -> output
    // stores are fully coalesced 2KB block writes per timestep.
    const int c_s  = tid >> 6;
    const int h1_s = tid & 63;

    // Row padded to 9 words per h1 to avoid 8-way smem bank conflicts on
    // the scan-side reads (stride 9 is odd -> full bank cycle).
    __shared__ float sm[KT][64 * 9];

    const float* inb  = in  + (size_t)b * (200 * T_STRIDE)
                            + (size_t)t_base * T_STRIDE + h2 * 8;
    float*       outb = out + (size_t)b * (200 * T_STRIDE)
                            + (size_t)t_base * T_STRIDE + h2 * 512;

    const int    l_idx = h1_l * 9 + c_l;
    const size_t l_off = (size_t)h1_l * 512 + c_l;
    const int    s_idx = h1_s * 9 + c_s;

    float v = 0.0f;

    for (int t0 = 0; t0 < CHUNK; t0 += KT) {
        // Stage KT timesteps (MLP = KT independent loads per thread)
        #pragma unroll
        for (int k = 0; k < KT; k++)
            sm[k][l_idx] = inb[(size_t)(t0 + k) * T_STRIDE + l_off];
        __syncthreads();

        // Sequential membrane scan + coalesced spike stores
        #pragma unroll
        for (int k = 0; k < KT; k++) {
            v += sm[k][s_idx];
            float spike = 0.0f;
            if (v > 2.0f) { spike = 1.0f; v = 0.0f; }
            outb[(size_t)(t0 + k) * T_STRIDE + tid] = spike;
        }
        __syncthreads();   // protect sm from next tile's loads
    }
}

extern "C" void kernel_launch(void* const* d_in, const int* in_sizes, int n_in,
                              void* d_out, int out_size) {
    const float* in  = (const float*)d_in[0];
    float*       out = (float*)d_out;
    iaf_kernel<<<512, 512>>>(in, out);
}